// round 7
// baseline (speedup 1.0000x reference)
#include <cuda_runtime.h>
#include <cuda_bf16.h>
#include <math.h>

// Problem constants
#define B_  8
#define L_  256
#define DM_ 1024
#define DI_ 2048
#define N_  16
#define K_  4
#define NL_ 4
#define DTR_ 128
#define P_  97
#define M_TOK (B_*L_)          // 2048 token rows
#define XPW_ (DTR_ + 2*N_)     // 160

// GEMM tiling
#define BM 128
#define BN 128
#define BK 16
#define SST 132                // smem row stride in words ([kp][m] layout, kp = k/2)

// pair widths
#define DMP (DM_/2)            // 512
#define DIP (DI_/2)            // 1024
#define DTRP (DTR_/2)          // 64
#define XPWP (XPW_/2)          // 80

// ---------------- scratch (static device globals; no allocation) ----------------
__device__ __align__(16) float g_h [M_TOK*DM_];
__device__ __align__(16) float g_xz[M_TOK*2*DI_];
__device__ __align__(16) float g_xb[M_TOK*DI_];
__device__ __align__(16) float g_xp[M_TOK*XPW_];
__device__ __align__(16) float g_dl[M_TOK*DI_];
__device__ __align__(16) float g_y [M_TOK*DI_];
__device__ __align__(16) float g_fin[B_*DM_];

// packed activations (uint2 per k-pair: {hi bf16x2, lo bf16x2})
__device__ __align__(16) uint2 g_xP [M_TOK*DMP];
__device__ __align__(16) uint2 g_xbP[M_TOK*DIP];
__device__ __align__(16) uint2 g_xpP[M_TOK*XPWP];
__device__ __align__(16) uint2 g_yP [M_TOK*DIP];
// packed weights
__device__ __align__(16) uint2 g_ipwP[NL_*2*DI_*DMP];
__device__ __align__(16) uint2 g_xpwP[NL_*XPW_*DIP];
__device__ __align__(16) uint2 g_dtwP[NL_*DI_*DTRP];
__device__ __align__(16) uint2 g_opwP[NL_*DM_*DIP];

// ---------------- bf16 split helpers ----------------
__device__ __forceinline__ uint2 split2_bf16(float x, float y) {
    __nv_bfloat16 hx = __float2bfloat16(x);
    __nv_bfloat16 hy = __float2bfloat16(y);
    float lx = x - __bfloat162float(hx);
    float ly = y - __bfloat162float(hy);
    __nv_bfloat162 hp = __halves2bfloat162(hx, hy);
    __nv_bfloat162 lp = __halves2bfloat162(__float2bfloat16(lx), __float2bfloat16(ly));
    unsigned hw, lw;
    hw = *reinterpret_cast<unsigned*>(&hp);
    lw = *reinterpret_cast<unsigned*>(&lp);
    return make_uint2(hw, lw);
}

__device__ __forceinline__ void mma_bf16(float* c, const unsigned* a, const unsigned* b) {
    asm volatile(
        "mma.sync.aligned.m16n8k16.row.col.f32.bf16.bf16.f32 "
        "{%0,%1,%2,%3}, {%4,%5,%6,%7}, {%8,%9}, {%0,%1,%2,%3};"
        : "+f"(c[0]), "+f"(c[1]), "+f"(c[2]), "+f"(c[3])
        : "r"(a[0]), "r"(a[1]), "r"(a[2]), "r"(a[3]), "r"(b[0]), "r"(b[1]));
}

// ---------------- generic fp32 -> packed split (grid-stride) ----------------
__global__ void pack_k(const float* __restrict__ src, uint2* __restrict__ dst, long npairs) {
    long i = (long)blockIdx.x * 256 + threadIdx.x;
    long stride = (long)gridDim.x * 256;
    for (; i < npairs; i += stride) {
        float2 v = reinterpret_cast<const float2*>(src)[i];
        dst[i] = split2_bf16(v.x, v.y);
    }
}

// ---------------- small utils ----------------
__global__ void zero_k(float* __restrict__ p, int n4) {
    int i = blockIdx.x * 256 + threadIdx.x;
    if (i < n4) reinterpret_cast<float4*>(p)[i] = make_float4(0,0,0,0);
}

// ---------------- embedding ----------------
__global__ void embed_k(const int* __restrict__ tok, const float* __restrict__ te,
                        const float* __restrict__ pe, float* __restrict__ h) {
    int row = blockIdx.x;
    int l = row & (L_ - 1);
    int t = tok[row];
    const float* tsrc = te + (long)t * DM_;
    const float* psrc = pe + (long)l * DM_;
    float* dst = h + (long)row * DM_;
    for (int d = threadIdx.x; d < DM_; d += 256)
        dst[d] = tsrc[d] + psrc[d];
}

// ---------------- layernorm -> packed output (row of 1024, 256 thr x float4) ------
__global__ void ln_pack_k(const float* __restrict__ in,
                          const float* __restrict__ w, const float* __restrict__ bb,
                          uint2* __restrict__ outP) {
    __shared__ float red[8];
    __shared__ float s_mean, s_rstd;
    int t = threadIdx.x;
    int row = blockIdx.x;
    float4 v = reinterpret_cast<const float4*>(in + (long)row * DM_)[t];
    float s = v.x + v.y + v.z + v.w;
#pragma unroll
    for (int o = 16; o; o >>= 1) s += __shfl_xor_sync(~0u, s, o);
    if ((t & 31) == 0) red[t >> 5] = s;
    __syncthreads();
    if (t < 32) {
        float x = (t < 8) ? red[t] : 0.f;
#pragma unroll
        for (int o = 4; o; o >>= 1) x += __shfl_xor_sync(~0u, x, o);
        if (t == 0) s_mean = x * (1.f/DM_);
    }
    __syncthreads();
    float mean = s_mean;
    float dx = v.x-mean, dy = v.y-mean, dz = v.z-mean, dw = v.w-mean;
    float q = dx*dx + dy*dy + dz*dz + dw*dw;
#pragma unroll
    for (int o = 16; o; o >>= 1) q += __shfl_xor_sync(~0u, q, o);
    if ((t & 31) == 0) red[t >> 5] = q;
    __syncthreads();
    if (t < 32) {
        float x = (t < 8) ? red[t] : 0.f;
#pragma unroll
        for (int o = 4; o; o >>= 1) x += __shfl_xor_sync(~0u, x, o);
        if (t == 0) s_rstd = rsqrtf(x * (1.f/DM_) + 1e-5f);
    }
    __syncthreads();
    float r = s_rstd;
    float4 wv = reinterpret_cast<const float4*>(w)[t];
    float4 bv = reinterpret_cast<const float4*>(bb)[t];
    float o0 = dx * r * wv.x + bv.x;
    float o1 = dy * r * wv.y + bv.y;
    float o2 = dz * r * wv.z + bv.z;
    float o3 = dw * r * wv.w + bv.w;
    uint2 p0 = split2_bf16(o0, o1);
    uint2 p1 = split2_bf16(o2, o3);
    reinterpret_cast<uint4*>(outP)[(long)row * (DMP/2) + t] =
        make_uint4(p0.x, p0.y, p1.x, p1.y);
}

// ---------------- plain layernorm (final; fp32 out) ----------------
__global__ void ln_k(const float* __restrict__ in, long istride,
                     float* __restrict__ out,
                     const float* __restrict__ w, const float* __restrict__ bb) {
    __shared__ float red[8];
    __shared__ float s_mean, s_rstd;
    int t = threadIdx.x;
    int row = blockIdx.x;
    const float* src = in + (long)row * istride;
    float v[4];
    float s = 0.f;
#pragma unroll
    for (int i = 0; i < 4; i++) { v[i] = src[t + i*256]; s += v[i]; }
#pragma unroll
    for (int o = 16; o; o >>= 1) s += __shfl_xor_sync(~0u, s, o);
    if ((t & 31) == 0) red[t >> 5] = s;
    __syncthreads();
    if (t < 32) {
        float x = (t < 8) ? red[t] : 0.f;
#pragma unroll
        for (int o = 4; o; o >>= 1) x += __shfl_xor_sync(~0u, x, o);
        if (t == 0) s_mean = x * (1.f/DM_);
    }
    __syncthreads();
    float mean = s_mean;
    float q = 0.f;
#pragma unroll
    for (int i = 0; i < 4; i++) { float d = v[i] - mean; q += d * d; }
#pragma unroll
    for (int o = 16; o; o >>= 1) q += __shfl_xor_sync(~0u, q, o);
    if ((t & 31) == 0) red[t >> 5] = q;
    __syncthreads();
    if (t < 32) {
        float x = (t < 8) ? red[t] : 0.f;
#pragma unroll
        for (int o = 4; o; o >>= 1) x += __shfl_xor_sync(~0u, x, o);
        if (t == 0) s_rstd = rsqrtf(x * (1.f/DM_) + 1e-5f);
    }
    __syncthreads();
    float r = s_rstd;
#pragma unroll
    for (int i = 0; i < 4; i++) {
        int idx = t + i*256;
        out[(long)row * DM_ + idx] = (v[i] - mean) * r * w[idx] + bb[idx];
    }
}

// ---------------- shared GEMM body macros (packed operands) ----------------
#define GEMM_DEPOSIT(AH, AL, BH, BL)                                  \
    {                                                                 \
        AH[kp0*SST + r0]        = av0q.x; AL[kp0*SST + r0]        = av0q.y; \
        AH[(kp0+1)*SST + r0]    = av0q.z; AL[(kp0+1)*SST + r0]    = av0q.w; \
        AH[kp0*SST + r0+64]     = av1q.x; AL[kp0*SST + r0+64]     = av1q.y; \
        AH[(kp0+1)*SST + r0+64] = av1q.z; AL[(kp0+1)*SST + r0+64] = av1q.w; \
        BH[kp0*SST + r0]        = bv0q.x; BL[kp0*SST + r0]        = bv0q.y; \
        BH[(kp0+1)*SST + r0]    = bv0q.z; BL[(kp0+1)*SST + r0]    = bv0q.w; \
        BH[kp0*SST + r0+64]     = bv1q.x; BL[kp0*SST + r0+64]     = bv1q.y; \
        BH[(kp0+1)*SST + r0+64] = bv1q.z; BL[(kp0+1)*SST + r0+64] = bv1q.w; \
    }

#define GEMM_COMPUTE(AH, AL, BH, BL)                                                   \
    {                                                                                  \
        unsigned bh[4][2], bl[4][2];                                                   \
        _Pragma("unroll")                                                              \
        for (int j = 0; j < 4; j++) {                                                  \
            int n = warpN + j*8 + grp;                                                 \
            bh[j][0] = BH[tig*SST + n];                                                \
            bh[j][1] = BH[(tig+4)*SST + n];                                            \
            bl[j][0] = BL[tig*SST + n];                                                \
            bl[j][1] = BL[(tig+4)*SST + n];                                            \
        }                                                                              \
        _Pragma("unroll")                                                              \
        for (int i = 0; i < 4; i++) {                                                  \
            int m = warpM + i*16 + grp;                                                \
            unsigned ah[4], al[4];                                                     \
            ah[0] = AH[tig*SST + m];     ah[1] = AH[tig*SST + m + 8];                  \
            ah[2] = AH[(tig+4)*SST + m]; ah[3] = AH[(tig+4)*SST + m + 8];              \
            al[0] = AL[tig*SST + m];     al[1] = AL[tig*SST + m + 8];                  \
            al[2] = AL[(tig+4)*SST + m]; al[3] = AL[(tig+4)*SST + m + 8];              \
            _Pragma("unroll")                                                          \
            for (int j = 0; j < 4; j++) mma_bf16(acc[i][j], ah, bh[j]);                \
            _Pragma("unroll")                                                          \
            for (int j = 0; j < 4; j++) mma_bf16(acc[i][j], ah, bl[j]);                \
            _Pragma("unroll")                                                          \
            for (int j = 0; j < 4; j++) mma_bf16(acc[i][j], al, bh[j]);                \
        }                                                                              \
    }

// ---------------- packed compensated GEMM: C[m,n] = sum_k A[m,k]*W[n,k] ----------------
// A, W pre-split packed uint2/k-pair. KdP = K/2 pairs. 128x128x16 tiles, 8 warps,
// double-buffered, 1 sync/k-tile. act: 0=none, 1=softplus.
__global__ __launch_bounds__(256, 2)
void gemm_p(int M, int N, int KdP,
            const uint2* __restrict__ A, int ldaP,
            const uint2* __restrict__ W, int ldbP,
            float* __restrict__ C, int ldc,
            const float* __restrict__ bias,
            const float* __restrict__ add, int ldadd,
            int act) {
    __shared__ unsigned Ahp[2][8*SST], Alp[2][8*SST];
    __shared__ unsigned Bhp[2][8*SST], Blp[2][8*SST];
    int tid = threadIdx.x;
    int lane = tid & 31, wid = tid >> 5;
    int warpM = (wid >> 2) * 64;
    int warpN = (wid & 3) * 32;
    int grp = lane >> 2, tig = lane & 3;

    int r0 = tid >> 2;
    int kp0 = (tid & 3) * 2;          // pair offset 0,2,4,6
    int gAr0 = blockIdx.y * BM + r0, gAr1 = gAr0 + 64;
    int gBr0 = blockIdx.x * BN + r0, gBr1 = gBr0 + 64;
    bool aOK0 = gAr0 < M, aOK1 = gAr1 < M;
    bool bOK0 = gBr0 < N, bOK1 = gBr1 < N;
    const uint2* Ap0 = A + (long)gAr0 * ldaP + kp0;
    const uint2* Ap1 = A + (long)gAr1 * ldaP + kp0;
    const uint2* Wp0 = W + (long)gBr0 * ldbP + kp0;
    const uint2* Wp1 = W + (long)gBr1 * ldbP + kp0;

    float acc[4][4][4];
#pragma unroll
    for (int i = 0; i < 4; i++)
#pragma unroll
        for (int j = 0; j < 4; j++)
#pragma unroll
            for (int q = 0; q < 4; q++) acc[i][j][q] = 0.f;

    const uint4 z4 = make_uint4(0,0,0,0);
    uint4 av0q, av1q, bv0q, bv1q;

    av0q = aOK0 ? *(const uint4*)(Ap0) : z4;
    av1q = aOK1 ? *(const uint4*)(Ap1) : z4;
    bv0q = bOK0 ? *(const uint4*)(Wp0) : z4;
    bv1q = bOK1 ? *(const uint4*)(Wp1) : z4;
    GEMM_DEPOSIT(Ahp[0], Alp[0], Bhp[0], Blp[0]);
    __syncthreads();

    int nst = KdP / 8;                // 8 pairs = 16 k per tile
    for (int kt = 0; kt < nst; kt++) {
        int cur = kt & 1;
        bool pf = (kt + 1) < nst;
        if (pf) {
            int k0 = (kt + 1) * 8;
            av0q = aOK0 ? *(const uint4*)(Ap0 + k0) : z4;
            av1q = aOK1 ? *(const uint4*)(Ap1 + k0) : z4;
            bv0q = bOK0 ? *(const uint4*)(Wp0 + k0) : z4;
            bv1q = bOK1 ? *(const uint4*)(Wp1 + k0) : z4;
        }
        if (cur == 0) { GEMM_COMPUTE(Ahp[0], Alp[0], Bhp[0], Blp[0]); }
        else          { GEMM_COMPUTE(Ahp[1], Alp[1], Bhp[1], Blp[1]); }
        if (pf) {
            if (cur == 0) { GEMM_DEPOSIT(Ahp[1], Alp[1], Bhp[1], Blp[1]); }
            else          { GEMM_DEPOSIT(Ahp[0], Alp[0], Bhp[0], Blp[0]); }
            __syncthreads();
        }
    }

#pragma unroll
    for (int i = 0; i < 4; i++) {
        int gm0 = blockIdx.y * BM + warpM + i*16 + grp;
#pragma unroll
        for (int j = 0; j < 4; j++) {
            int gn = blockIdx.x * BN + warpN + j*8 + 2*tig;
#pragma unroll
            for (int half = 0; half < 2; half++) {
                int gm = gm0 + half*8;
                if (gm >= M) continue;
#pragma unroll
                for (int q = 0; q < 2; q++) {
                    int n = gn + q;
                    if (n >= N) continue;
                    float v = acc[i][j][half*2 + q];
                    if (bias) v += bias[n];
                    if (act == 1) v = (v > 20.f) ? v : log1pf(expf(v));
                    if (add) v += add[(long)gm * ldadd + n];
                    C[(long)gm * ldc + n] = v;
                }
            }
        }
    }
}

// ---------------- packed split-K GEMM: C += partial (atomicAdd) ----------------
__global__ __launch_bounds__(256, 2)
void gemm_p_sk(int M, int N, int kcntP,
               const uint2* __restrict__ A, int ldaP,
               const uint2* __restrict__ W, int ldbP,
               float* __restrict__ C, int ldc) {
    __shared__ unsigned Ahp[2][8*SST], Alp[2][8*SST];
    __shared__ unsigned Bhp[2][8*SST], Blp[2][8*SST];
    int tid = threadIdx.x;
    int lane = tid & 31, wid = tid >> 5;
    int warpM = (wid >> 2) * 64;
    int warpN = (wid & 3) * 32;
    int grp = lane >> 2, tig = lane & 3;

    long kbeg = (long)blockIdx.z * kcntP;
    A += kbeg; W += kbeg;

    int r0 = tid >> 2;
    int kp0 = (tid & 3) * 2;
    int gAr0 = blockIdx.y * BM + r0, gAr1 = gAr0 + 64;
    int gBr0 = blockIdx.x * BN + r0, gBr1 = gBr0 + 64;
    bool aOK0 = gAr0 < M, aOK1 = gAr1 < M;
    bool bOK0 = gBr0 < N, bOK1 = gBr1 < N;
    const uint2* Ap0 = A + (long)gAr0 * ldaP + kp0;
    const uint2* Ap1 = A + (long)gAr1 * ldaP + kp0;
    const uint2* Wp0 = W + (long)gBr0 * ldbP + kp0;
    const uint2* Wp1 = W + (long)gBr1 * ldbP + kp0;

    float acc[4][4][4];
#pragma unroll
    for (int i = 0; i < 4; i++)
#pragma unroll
        for (int j = 0; j < 4; j++)
#pragma unroll
            for (int q = 0; q < 4; q++) acc[i][j][q] = 0.f;

    const uint4 z4 = make_uint4(0,0,0,0);
    uint4 av0q, av1q, bv0q, bv1q;

    av0q = aOK0 ? *(const uint4*)(Ap0) : z4;
    av1q = aOK1 ? *(const uint4*)(Ap1) : z4;
    bv0q = bOK0 ? *(const uint4*)(Wp0) : z4;
    bv1q = bOK1 ? *(const uint4*)(Wp1) : z4;
    GEMM_DEPOSIT(Ahp[0], Alp[0], Bhp[0], Blp[0]);
    __syncthreads();

    int nst = kcntP / 8;
    for (int kt = 0; kt < nst; kt++) {
        int cur = kt & 1;
        bool pf = (kt + 1) < nst;
        if (pf) {
            int k0 = (kt + 1) * 8;
            av0q = aOK0 ? *(const uint4*)(Ap0 + k0) : z4;
            av1q = aOK1 ? *(const uint4*)(Ap1 + k0) : z4;
            bv0q = bOK0 ? *(const uint4*)(Wp0 + k0) : z4;
            bv1q = bOK1 ? *(const uint4*)(Wp1 + k0) : z4;
        }
        if (cur == 0) { GEMM_COMPUTE(Ahp[0], Alp[0], Bhp[0], Blp[0]); }
        else          { GEMM_COMPUTE(Ahp[1], Alp[1], Bhp[1], Blp[1]); }
        if (pf) {
            if (cur == 0) { GEMM_DEPOSIT(Ahp[1], Alp[1], Bhp[1], Blp[1]); }
            else          { GEMM_DEPOSIT(Ahp[0], Alp[0], Bhp[0], Blp[0]); }
            __syncthreads();
        }
    }

#pragma unroll
    for (int i = 0; i < 4; i++) {
        int gm0 = blockIdx.y * BM + warpM + i*16 + grp;
#pragma unroll
        for (int j = 0; j < 4; j++) {
            int gn = blockIdx.x * BN + warpN + j*8 + 2*tig;
#pragma unroll
            for (int half = 0; half < 2; half++) {
                int gm = gm0 + half*8;
                if (gm >= M) continue;
#pragma unroll
                for (int q = 0; q < 2; q++) {
                    int n = gn + q;
                    if (n >= N) continue;
                    atomicAdd(&C[(long)gm * ldc + n], acc[i][j][half*2 + q]);
                }
            }
        }
    }
}

// ---------------- causal depthwise conv (K=4) + SiLU, fp32 + packed out ----------------
// one thread per d-pair
__global__ void conv_silu_k(const float* __restrict__ xz, const float* __restrict__ cw,
                            const float* __restrict__ cb, float* __restrict__ xb,
                            uint2* __restrict__ xbP) {
    long pidx = (long)blockIdx.x * 256 + threadIdx.x;   // < M_TOK*DIP
    int ep = (int)(pidx & (DIP - 1));
    long bl = pidx >> 10;                // / DIP
    int l = (int)(bl & (L_ - 1));
    int d0 = ep * 2, d1 = d0 + 1;
    float a0 = cb[d0], a1 = cb[d1];
#pragma unroll
    for (int k = 0; k < K_; k++) {
        int lp = l + k - (K_ - 1);
        if (lp >= 0) {
            const float* src = xz + (bl + (k - (K_-1))) * (2*DI_);
            a0 = fmaf(cw[d0*K_ + k], src[d0], a0);
            a1 = fmaf(cw[d1*K_ + k], src[d1], a1);
        }
    }
    a0 = a0 / (1.f + expf(-a0));
    a1 = a1 / (1.f + expf(-a1));
    reinterpret_cast<float2*>(xb)[pidx] = make_float2(a0, a1);
    xbP[pidx] = split2_bf16(a0, a1);
}

// ---------------- selective SSM scan + D skip + z-gating ----------------
__global__ void ssm_scan_k(const float* __restrict__ xb, const float* __restrict__ xp,
                           const float* __restrict__ dl, const float* __restrict__ xz,
                           const float* __restrict__ Alog, const float* __restrict__ Dp,
                           float* __restrict__ y) {
    int t = threadIdx.x;
    int g = t >> 4, lane = t & 15;
    int ch = blockIdx.x * 16 + g;
    int b = ch >> 11;
    int d = ch & (DI_ - 1);
    float A = -expf(Alog[d*N_ + lane]);
    float Dv = Dp[d];
    float h = 0.f;
    long rowbase = (long)b * L_;
    for (int l = 0; l < L_; l++) {
        long r = rowbase + l;
        float dv = dl[r*DI_ + d];
        float xv = xb[r*DI_ + d];
        float Bv = xp[r*XPW_ + DTR_ + lane];
        float Cv = xp[r*XPW_ + DTR_ + N_ + lane];
        h = fmaf(expf(dv * A), h, dv * Bv * xv);
        float c = h * Cv;
        c += __shfl_xor_sync(~0u, c, 8);
        c += __shfl_xor_sync(~0u, c, 4);
        c += __shfl_xor_sync(~0u, c, 2);
        c += __shfl_xor_sync(~0u, c, 1);
        if (lane == 0) {
            float z = xz[r*(2*DI_) + DI_ + d];
            float yv = c + xv * Dv;
            y[r*DI_ + d] = yv * (z / (1.f + expf(-z)));
        }
    }
}

// ---------------- head ----------------
__global__ void head_k(const float* __restrict__ fin, const float* __restrict__ hw,
                       float* __restrict__ out) {
    int wid = blockIdx.x * 8 + (threadIdx.x >> 5);
    int lane = threadIdx.x & 31;
    if (wid >= B_ * P_) return;
    int b = wid / P_, p = wid % P_;
    const float* a = fin + (long)b * DM_;
    const float* w = hw + (long)p * DM_;
    float s = 0.f;
    for (int k = lane; k < DM_; k += 32) s = fmaf(a[k], w[k], s);
#pragma unroll
    for (int o = 16; o; o >>= 1) s += __shfl_xor_sync(~0u, s, o);
    if (lane == 0) out[wid] = s;
}

// ---------------- launch ----------------
extern "C" void kernel_launch(void* const* d_in, const int* in_sizes, int n_in,
                              void* d_out, int out_size) {
    const int*   tokens    = (const int*)  d_in[0];
    const float* tok_emb   = (const float*)d_in[1];
    const float* pos_emb   = (const float*)d_in[2];
    const float* ln_w      = (const float*)d_in[3];
    const float* ln_b      = (const float*)d_in[4];
    const float* in_proj_w = (const float*)d_in[5];
    const float* conv_w    = (const float*)d_in[6];
    const float* conv_b    = (const float*)d_in[7];
    const float* xproj_w   = (const float*)d_in[8];
    const float* dt_w      = (const float*)d_in[9];
    const float* dt_b      = (const float*)d_in[10];
    const float* A_log     = (const float*)d_in[11];
    const float* D_param   = (const float*)d_in[12];
    const float* out_proj_w= (const float*)d_in[13];
    const float* fnorm_w   = (const float*)d_in[14];
    const float* fnorm_b   = (const float*)d_in[15];
    const float* head_w    = (const float*)d_in[16];
    float* out = (float*)d_out;

    void *ph, *pxz, *pxb, *pxp, *pdl, *py, *pfin;
    void *pxP, *pxbP, *pxpP, *pyP, *pipw, *pxpw, *pdtw, *popw;
    cudaGetSymbolAddress(&ph,  g_h);
    cudaGetSymbolAddress(&pxz, g_xz);
    cudaGetSymbolAddress(&pxb, g_xb);
    cudaGetSymbolAddress(&pxp, g_xp);
    cudaGetSymbolAddress(&pdl, g_dl);
    cudaGetSymbolAddress(&py,  g_y);
    cudaGetSymbolAddress(&pfin,g_fin);
    cudaGetSymbolAddress(&pxP, g_xP);
    cudaGetSymbolAddress(&pxbP,g_xbP);
    cudaGetSymbolAddress(&pxpP,g_xpP);
    cudaGetSymbolAddress(&pyP, g_yP);
    cudaGetSymbolAddress(&pipw,g_ipwP);
    cudaGetSymbolAddress(&pxpw,g_xpwP);
    cudaGetSymbolAddress(&pdtw,g_dtwP);
    cudaGetSymbolAddress(&popw,g_opwP);
    float* h  = (float*)ph;   float* xz = (float*)pxz;
    float* xb = (float*)pxb;  float* xp = (float*)pxp;
    float* dl = (float*)pdl;  float* y  = (float*)py;
    float* fin= (float*)pfin;
    uint2* xP  = (uint2*)pxP;   uint2* xbP = (uint2*)pxbP;
    uint2* xpP = (uint2*)pxpP;  uint2* yP  = (uint2*)pyP;
    uint2* ipwP= (uint2*)pipw;  uint2* xpwP= (uint2*)pxpw;
    uint2* dtwP= (uint2*)pdtw;  uint2* opwP= (uint2*)popw;

    // pack all weights (once per launch; overlaps nothing but is ~50us total)
    pack_k<<<8192, 256>>>(in_proj_w, ipwP, (long)NL_*2*DI_*DMP);
    pack_k<<<2048, 256>>>(xproj_w,   xpwP, (long)NL_*XPW_*DIP);
    pack_k<<<2048, 256>>>(dt_w,      dtwP, (long)NL_*DI_*DTRP);
    pack_k<<<8192, 256>>>(out_proj_w,opwP, (long)NL_*DM_*DIP);

    embed_k<<<M_TOK, 256>>>(tokens, tok_emb, pos_emb, h);

    for (int i = 0; i < NL_; i++) {
        // 1. layernorm -> packed x
        ln_pack_k<<<M_TOK, 256>>>(h, ln_w + i*DM_, ln_b + i*DM_, xP);
        // 2. in_proj: 2048 x 4096 x 1024
        gemm_p<<<dim3(32, 16), 256>>>(M_TOK, 2*DI_, DMP,
            xP, DMP, ipwP + (long)i*2*DI_*DMP, DMP,
            xz, 2*DI_, nullptr, nullptr, 0, 0);
        // 3. conv + silu -> xb fp32 + packed
        conv_silu_k<<<(M_TOK*DIP)/256, 256>>>(xz, conv_w + (long)i*DI_*K_,
            conv_b + (long)i*DI_, xb, xbP);
        // 4. xproj: 2048 x 160 x 2048, split-K 8 into zeroed xp
        zero_k<<<(M_TOK*XPW_/4 + 255)/256, 256>>>(xp, M_TOK*XPW_/4);
        gemm_p_sk<<<dim3(2, 16, 8), 256>>>(M_TOK, XPW_, DIP/8,
            xbP, DIP, xpwP + (long)i*XPW_*DIP, DIP,
            xp, XPW_);
        // 5. pack xp (dt_r part is pairs 0..63 of each row)
        pack_k<<<640, 256>>>(xp, xpP, (long)M_TOK*XPWP);
        // 6. delta = softplus(dt_r @ dtw.T + dtb): 2048 x 2048 x 128
        gemm_p<<<dim3(16, 16), 256>>>(M_TOK, DI_, DTRP,
            xpP, XPWP, dtwP + (long)i*DI_*DTRP, DTRP,
            dl, DI_, dt_b + (long)i*DI_, nullptr, 0, 1);
        // 7. SSM scan
        ssm_scan_k<<<(B_*DI_)/16, 256>>>(xb, xp, dl, xz,
            A_log + (long)i*DI_*N_, D_param + (long)i*DI_, y);
        // 8. pack y
        pack_k<<<8192, 256>>>(y, yP, (long)M_TOK*DIP);
        // 9. out_proj + residual: split-K 2, atomic into h (holds residual)
        gemm_p_sk<<<dim3(8, 16, 2), 256>>>(M_TOK, DM_, DIP/2,
            yP, DIP, opwP + (long)i*DM_*DIP, DIP,
            h, DM_);
    }

    ln_k<<<B_, 256>>>(h + (long)(L_-1)*DM_, (long)L_*DM_, fin, fnorm_w, fnorm_b);
    head_k<<<P_, 256>>>(fin, head_w, out);
}

// round 10
// speedup vs baseline: 1.2356x; 1.2356x over previous
#include <cuda_runtime.h>
#include <cuda_bf16.h>
#include <math.h>

// Problem constants
#define B_  8
#define L_  256
#define DM_ 1024
#define DI_ 2048
#define N_  16
#define K_  4
#define NL_ 4
#define DTR_ 128
#define P_  97
#define M_TOK (B_*L_)          // 2048 token rows
#define XPW_ (DTR_ + 2*N_)     // 160

// GEMM tiling
#define BM 128
#define BN 128
#define BK 16
#define SST 132                // smem row stride in words ([kp][m] layout, kp = k/2)

// ---------------- scratch (static device globals; no allocation) ----------------
__device__ __align__(16) float g_h [M_TOK*DM_];
__device__ __align__(16) float g_x [M_TOK*DM_];
__device__ __align__(16) float g_xz[M_TOK*2*DI_];
__device__ __align__(16) float g_xb[M_TOK*DI_];
__device__ __align__(16) float g_xp[M_TOK*XPW_];
__device__ __align__(16) float g_dl[M_TOK*DI_];
__device__ __align__(16) float g_y [M_TOK*DI_];
__device__ __align__(16) float g_fin[B_*DM_];

// ---------------- small utils ----------------
__global__ void zero_k(float* __restrict__ p, int n4) {
    int i = blockIdx.x * 256 + threadIdx.x;
    if (i < n4) reinterpret_cast<float4*>(p)[i] = make_float4(0,0,0,0);
}

// ---------------- embedding ----------------
__global__ void embed_k(const int* __restrict__ tok, const float* __restrict__ te,
                        const float* __restrict__ pe, float* __restrict__ h) {
    int row = blockIdx.x;
    int l = row & (L_ - 1);
    int t = tok[row];
    const float* tsrc = te + (long)t * DM_;
    const float* psrc = pe + (long)l * DM_;
    float* dst = h + (long)row * DM_;
    for (int d = threadIdx.x; d < DM_; d += 256)
        dst[d] = tsrc[d] + psrc[d];
}

// ---------------- layernorm ----------------
__global__ void ln_k(const float* __restrict__ in, long istride,
                     float* __restrict__ out, long ostride,
                     const float* __restrict__ w, const float* __restrict__ bb) {
    __shared__ float red[8];
    __shared__ float s_mean, s_rstd;
    int t = threadIdx.x;
    int row = blockIdx.x;
    const float* src = in + (long)row * istride;
    float v[4];
    float s = 0.f;
#pragma unroll
    for (int i = 0; i < 4; i++) { v[i] = src[t + i*256]; s += v[i]; }
#pragma unroll
    for (int o = 16; o; o >>= 1) s += __shfl_xor_sync(~0u, s, o);
    if ((t & 31) == 0) red[t >> 5] = s;
    __syncthreads();
    if (t < 32) {
        float x = (t < 8) ? red[t] : 0.f;
#pragma unroll
        for (int o = 4; o; o >>= 1) x += __shfl_xor_sync(~0u, x, o);
        if (t == 0) s_mean = x * (1.f/DM_);
    }
    __syncthreads();
    float mean = s_mean;
    float q = 0.f;
#pragma unroll
    for (int i = 0; i < 4; i++) { float d = v[i] - mean; q += d * d; }
#pragma unroll
    for (int o = 16; o; o >>= 1) q += __shfl_xor_sync(~0u, q, o);
    if ((t & 31) == 0) red[t >> 5] = q;
    __syncthreads();
    if (t < 32) {
        float x = (t < 8) ? red[t] : 0.f;
#pragma unroll
        for (int o = 4; o; o >>= 1) x += __shfl_xor_sync(~0u, x, o);
        if (t == 0) s_rstd = rsqrtf(x * (1.f/DM_) + 1e-5f);
    }
    __syncthreads();
    float r = s_rstd;
    float* dst = out + (long)row * ostride;
#pragma unroll
    for (int i = 0; i < 4; i++) {
        int idx = t + i*256;
        dst[idx] = (v[i] - mean) * r * w[idx] + bb[idx];
    }
}

// ---------------- bf16 split helpers ----------------
__device__ __forceinline__ uint2 split2_bf16(float x, float y) {
    __nv_bfloat16 hx = __float2bfloat16(x);
    __nv_bfloat16 hy = __float2bfloat16(y);
    float lx = x - __bfloat162float(hx);
    float ly = y - __bfloat162float(hy);
    __nv_bfloat162 hp = __halves2bfloat162(hx, hy);
    __nv_bfloat162 lp = __halves2bfloat162(__float2bfloat16(lx), __float2bfloat16(ly));
    unsigned hw, lw;
    hw = *reinterpret_cast<unsigned*>(&hp);
    lw = *reinterpret_cast<unsigned*>(&lp);
    return make_uint2(hw, lw);
}

__device__ __forceinline__ void mma_bf16(float* c, const unsigned* a, const unsigned* b) {
    asm volatile(
        "mma.sync.aligned.m16n8k16.row.col.f32.bf16.bf16.f32 "
        "{%0,%1,%2,%3}, {%4,%5,%6,%7}, {%8,%9}, {%0,%1,%2,%3};"
        : "+f"(c[0]), "+f"(c[1]), "+f"(c[2]), "+f"(c[3])
        : "r"(a[0]), "r"(a[1]), "r"(a[2]), "r"(a[3]), "r"(b[0]), "r"(b[1]));
}

// fast softplus: v>20 -> v, else log(1+exp(v)) via MUFU
__device__ __forceinline__ float softplus_f(float v) {
    return (v > 20.f) ? v : __logf(1.f + __expf(v));
}

// shared compute body macro: one 128x128x16 step from buffer `cur`
#define GEMM_DEPOSIT(AH, AL, BH, BL)                                                   \
    {                                                                                  \
        uint2 s;                                                                       \
        s = split2_bf16(av0.x, av0.y); AH[kp0*SST + r0] = s.x; AL[kp0*SST + r0] = s.y; \
        s = split2_bf16(av0.z, av0.w); AH[(kp0+1)*SST + r0] = s.x; AL[(kp0+1)*SST + r0] = s.y; \
        s = split2_bf16(av1.x, av1.y); AH[kp0*SST + r0+64] = s.x; AL[kp0*SST + r0+64] = s.y; \
        s = split2_bf16(av1.z, av1.w); AH[(kp0+1)*SST + r0+64] = s.x; AL[(kp0+1)*SST + r0+64] = s.y; \
        s = split2_bf16(bv0.x, bv0.y); BH[kp0*SST + r0] = s.x; BL[kp0*SST + r0] = s.y; \
        s = split2_bf16(bv0.z, bv0.w); BH[(kp0+1)*SST + r0] = s.x; BL[(kp0+1)*SST + r0] = s.y; \
        s = split2_bf16(bv1.x, bv1.y); BH[kp0*SST + r0+64] = s.x; BL[kp0*SST + r0+64] = s.y; \
        s = split2_bf16(bv1.z, bv1.w); BH[(kp0+1)*SST + r0+64] = s.x; BL[(kp0+1)*SST + r0+64] = s.y; \
    }

#define GEMM_COMPUTE(AH, AL, BH, BL)                                                   \
    {                                                                                  \
        unsigned bh[4][2], bl[4][2];                                                   \
        _Pragma("unroll")                                                              \
        for (int j = 0; j < 4; j++) {                                                  \
            int n = warpN + j*8 + grp;                                                 \
            bh[j][0] = BH[tig*SST + n];                                                \
            bh[j][1] = BH[(tig+4)*SST + n];                                            \
            bl[j][0] = BL[tig*SST + n];                                                \
            bl[j][1] = BL[(tig+4)*SST + n];                                            \
        }                                                                              \
        _Pragma("unroll")                                                              \
        for (int i = 0; i < 4; i++) {                                                  \
            int m = warpM + i*16 + grp;                                                \
            unsigned ah[4], al[4];                                                     \
            ah[0] = AH[tig*SST + m];     ah[1] = AH[tig*SST + m + 8];                  \
            ah[2] = AH[(tig+4)*SST + m]; ah[3] = AH[(tig+4)*SST + m + 8];              \
            al[0] = AL[tig*SST + m];     al[1] = AL[tig*SST + m + 8];                  \
            al[2] = AL[(tig+4)*SST + m]; al[3] = AL[(tig+4)*SST + m + 8];              \
            _Pragma("unroll")                                                          \
            for (int j = 0; j < 4; j++) mma_bf16(acc[i][j], ah, bh[j]);                \
            _Pragma("unroll")                                                          \
            for (int j = 0; j < 4; j++) mma_bf16(acc[i][j], ah, bl[j]);                \
            _Pragma("unroll")                                                          \
            for (int j = 0; j < 4; j++) mma_bf16(acc[i][j], al, bh[j]);                \
        }                                                                              \
    }

// ---------------- bf16x2 compensated GEMM (double-buffered): C = A @ W^T ----------------
__global__ __launch_bounds__(256, 2)
void gemm_bf16c(int M, int N, int Kd,
                const float* __restrict__ A, int lda,
                const float* __restrict__ W, int ldb,
                float* __restrict__ C, int ldc,
                const float* __restrict__ bias,
                const float* __restrict__ add, int ldadd,
                int act) {
    __shared__ unsigned Ahp[2][8*SST], Alp[2][8*SST];
    __shared__ unsigned Bhp[2][8*SST], Blp[2][8*SST];
    int tid = threadIdx.x;
    int lane = tid & 31, wid = tid >> 5;
    int warpM = (wid >> 2) * 64;
    int warpN = (wid & 3) * 32;
    int grp = lane >> 2, tig = lane & 3;

    int r0 = tid >> 2;
    int c4 = (tid & 3) * 4;
    int kp0 = c4 >> 1;
    int gAr0 = blockIdx.y * BM + r0, gAr1 = gAr0 + 64;
    int gBr0 = blockIdx.x * BN + r0, gBr1 = gBr0 + 64;
    bool aOK0 = gAr0 < M, aOK1 = gAr1 < M;
    bool bOK0 = gBr0 < N, bOK1 = gBr1 < N;
    const float* Ap0 = A + (long)gAr0 * lda + c4;
    const float* Ap1 = A + (long)gAr1 * lda + c4;
    const float* Wp0 = W + (long)gBr0 * ldb + c4;
    const float* Wp1 = W + (long)gBr1 * ldb + c4;

    float acc[4][4][4];
#pragma unroll
    for (int i = 0; i < 4; i++)
#pragma unroll
        for (int j = 0; j < 4; j++)
#pragma unroll
            for (int q = 0; q < 4; q++) acc[i][j][q] = 0.f;

    const float4 z4 = make_float4(0,0,0,0);
    float4 av0, av1, bv0, bv1;

    av0 = aOK0 ? *(const float4*)(Ap0) : z4;
    av1 = aOK1 ? *(const float4*)(Ap1) : z4;
    bv0 = bOK0 ? *(const float4*)(Wp0) : z4;
    bv1 = bOK1 ? *(const float4*)(Wp1) : z4;
    GEMM_DEPOSIT(Ahp[0], Alp[0], Bhp[0], Blp[0]);
    __syncthreads();

    int nst = Kd / BK;
    for (int kt = 0; kt < nst; kt++) {
        int cur = kt & 1;
        bool pf = (kt + 1) < nst;
        if (pf) {
            int k0 = (kt + 1) * BK;
            av0 = aOK0 ? *(const float4*)(Ap0 + k0) : z4;
            av1 = aOK1 ? *(const float4*)(Ap1 + k0) : z4;
            bv0 = bOK0 ? *(const float4*)(Wp0 + k0) : z4;
            bv1 = bOK1 ? *(const float4*)(Wp1 + k0) : z4;
        }
        if (cur == 0) { GEMM_COMPUTE(Ahp[0], Alp[0], Bhp[0], Blp[0]); }
        else          { GEMM_COMPUTE(Ahp[1], Alp[1], Bhp[1], Blp[1]); }
        if (pf) {
            if (cur == 0) { GEMM_DEPOSIT(Ahp[1], Alp[1], Bhp[1], Blp[1]); }
            else          { GEMM_DEPOSIT(Ahp[0], Alp[0], Bhp[0], Blp[0]); }
            __syncthreads();
        }
    }

#pragma unroll
    for (int i = 0; i < 4; i++) {
        int gm0 = blockIdx.y * BM + warpM + i*16 + grp;
#pragma unroll
        for (int j = 0; j < 4; j++) {
            int gn = blockIdx.x * BN + warpN + j*8 + 2*tig;
#pragma unroll
            for (int half = 0; half < 2; half++) {
                int gm = gm0 + half*8;
                if (gm >= M) continue;
#pragma unroll
                for (int q = 0; q < 2; q++) {
                    int n = gn + q;
                    if (n >= N) continue;
                    float v = acc[i][j][half*2 + q];
                    if (bias) v += bias[n];
                    if (act == 1) v = softplus_f(v);
                    if (add) v += add[(long)gm * ldadd + n];
                    C[(long)gm * ldc + n] = v;
                }
            }
        }
    }
}

// ---------------- split-K variant: C += partial (atomicAdd epilogue) ----------------
__global__ __launch_bounds__(256, 2)
void gemm_bf16c_sk(int M, int N, int kcnt,
                   const float* __restrict__ A, int lda,
                   const float* __restrict__ W, int ldb,
                   float* __restrict__ C, int ldc) {
    __shared__ unsigned Ahp[2][8*SST], Alp[2][8*SST];
    __shared__ unsigned Bhp[2][8*SST], Blp[2][8*SST];
    int tid = threadIdx.x;
    int lane = tid & 31, wid = tid >> 5;
    int warpM = (wid >> 2) * 64;
    int warpN = (wid & 3) * 32;
    int grp = lane >> 2, tig = lane & 3;

    long kbeg = (long)blockIdx.z * kcnt;
    A += kbeg; W += kbeg;

    int r0 = tid >> 2;
    int c4 = (tid & 3) * 4;
    int kp0 = c4 >> 1;
    int gAr0 = blockIdx.y * BM + r0, gAr1 = gAr0 + 64;
    int gBr0 = blockIdx.x * BN + r0, gBr1 = gBr0 + 64;
    bool aOK0 = gAr0 < M, aOK1 = gAr1 < M;
    bool bOK0 = gBr0 < N, bOK1 = gBr1 < N;
    const float* Ap0 = A + (long)gAr0 * lda + c4;
    const float* Ap1 = A + (long)gAr1 * lda + c4;
    const float* Wp0 = W + (long)gBr0 * ldb + c4;
    const float* Wp1 = W + (long)gBr1 * ldb + c4;

    float acc[4][4][4];
#pragma unroll
    for (int i = 0; i < 4; i++)
#pragma unroll
        for (int j = 0; j < 4; j++)
#pragma unroll
            for (int q = 0; q < 4; q++) acc[i][j][q] = 0.f;

    const float4 z4 = make_float4(0,0,0,0);
    float4 av0, av1, bv0, bv1;

    av0 = aOK0 ? *(const float4*)(Ap0) : z4;
    av1 = aOK1 ? *(const float4*)(Ap1) : z4;
    bv0 = bOK0 ? *(const float4*)(Wp0) : z4;
    bv1 = bOK1 ? *(const float4*)(Wp1) : z4;
    GEMM_DEPOSIT(Ahp[0], Alp[0], Bhp[0], Blp[0]);
    __syncthreads();

    int nst = kcnt / BK;
    for (int kt = 0; kt < nst; kt++) {
        int cur = kt & 1;
        bool pf = (kt + 1) < nst;
        if (pf) {
            int k0 = (kt + 1) * BK;
            av0 = aOK0 ? *(const float4*)(Ap0 + k0) : z4;
            av1 = aOK1 ? *(const float4*)(Ap1 + k0) : z4;
            bv0 = bOK0 ? *(const float4*)(Wp0 + k0) : z4;
            bv1 = bOK1 ? *(const float4*)(Wp1 + k0) : z4;
        }
        if (cur == 0) { GEMM_COMPUTE(Ahp[0], Alp[0], Bhp[0], Blp[0]); }
        else          { GEMM_COMPUTE(Ahp[1], Alp[1], Bhp[1], Blp[1]); }
        if (pf) {
            if (cur == 0) { GEMM_DEPOSIT(Ahp[1], Alp[1], Bhp[1], Blp[1]); }
            else          { GEMM_DEPOSIT(Ahp[0], Alp[0], Bhp[0], Blp[0]); }
            __syncthreads();
        }
    }

#pragma unroll
    for (int i = 0; i < 4; i++) {
        int gm0 = blockIdx.y * BM + warpM + i*16 + grp;
#pragma unroll
        for (int j = 0; j < 4; j++) {
            int gn = blockIdx.x * BN + warpN + j*8 + 2*tig;
#pragma unroll
            for (int half = 0; half < 2; half++) {
                int gm = gm0 + half*8;
                if (gm >= M) continue;
#pragma unroll
                for (int q = 0; q < 2; q++) {
                    int n = gn + q;
                    if (n >= N) continue;
                    atomicAdd(&C[(long)gm * ldc + n], acc[i][j][half*2 + q]);
                }
            }
        }
    }
}

// ---------------- causal depthwise conv (K=4) + SiLU (fast sigmoid) ----------------
__global__ void conv_silu_k(const float* __restrict__ xz, const float* __restrict__ cw,
                            const float* __restrict__ cb, float* __restrict__ xb) {
    long idx = (long)blockIdx.x * 256 + threadIdx.x;
    int d = idx & (DI_ - 1);
    long bl = idx >> 11;
    int l = (int)(bl & (L_ - 1));
    float acc = cb[d];
#pragma unroll
    for (int k = 0; k < K_; k++) {
        int lp = l + k - (K_ - 1);
        if (lp >= 0)
            acc = fmaf(cw[d*K_ + k], xz[(bl + (k - (K_-1))) * (2*DI_) + d], acc);
    }
    acc = __fdividef(acc, 1.f + __expf(-acc));
    xb[idx] = acc;
}

// ---------------- selective SSM scan + D skip + z-gating (fast exp) ----------------
__global__ void ssm_scan_k(const float* __restrict__ xb, const float* __restrict__ xp,
                           const float* __restrict__ dl, const float* __restrict__ xz,
                           const float* __restrict__ Alog, const float* __restrict__ Dp,
                           float* __restrict__ y) {
    int t = threadIdx.x;
    int g = t >> 4, lane = t & 15;
    int ch = blockIdx.x * 16 + g;
    int b = ch >> 11;
    int d = ch & (DI_ - 1);
    float A = -__expf(Alog[d*N_ + lane]);
    float Dv = Dp[d];
    float h = 0.f;
    long rowbase = (long)b * L_;
    const float* dlp = dl + rowbase*DI_ + d;
    const float* xbp = xb + rowbase*DI_ + d;
    const float* Bp  = xp + rowbase*XPW_ + DTR_ + lane;
    const float* zp  = xz + rowbase*(2*DI_) + DI_ + d;
    float* yp = y + rowbase*DI_ + d;
    for (int l = 0; l < L_; l++) {
        float dv = dlp[(long)l*DI_];
        float xv = xbp[(long)l*DI_];
        float Bv = Bp[(long)l*XPW_];
        float Cv = Bp[(long)l*XPW_ + N_];
        h = fmaf(__expf(dv * A), h, dv * Bv * xv);
        float c = h * Cv;
        c += __shfl_xor_sync(~0u, c, 8);
        c += __shfl_xor_sync(~0u, c, 4);
        c += __shfl_xor_sync(~0u, c, 2);
        c += __shfl_xor_sync(~0u, c, 1);
        if (lane == 0) {
            float z = zp[(long)l*(2*DI_)];
            float yv = c + xv * Dv;
            yp[(long)l*DI_] = yv * __fdividef(z, 1.f + __expf(-z));
        }
    }
}

// ---------------- head ----------------
__global__ void head_k(const float* __restrict__ fin, const float* __restrict__ hw,
                       float* __restrict__ out) {
    int wid = blockIdx.x * 8 + (threadIdx.x >> 5);
    int lane = threadIdx.x & 31;
    if (wid >= B_ * P_) return;
    int b = wid / P_, p = wid % P_;
    const float* a = fin + (long)b * DM_;
    const float* w = hw + (long)p * DM_;
    float s = 0.f;
    for (int k = lane; k < DM_; k += 32) s = fmaf(a[k], w[k], s);
#pragma unroll
    for (int o = 16; o; o >>= 1) s += __shfl_xor_sync(~0u, s, o);
    if (lane == 0) out[wid] = s;
}

// ---------------- launch ----------------
extern "C" void kernel_launch(void* const* d_in, const int* in_sizes, int n_in,
                              void* d_out, int out_size) {
    const int*   tokens    = (const int*)  d_in[0];
    const float* tok_emb   = (const float*)d_in[1];
    const float* pos_emb   = (const float*)d_in[2];
    const float* ln_w      = (const float*)d_in[3];
    const float* ln_b      = (const float*)d_in[4];
    const float* in_proj_w = (const float*)d_in[5];
    const float* conv_w    = (const float*)d_in[6];
    const float* conv_b    = (const float*)d_in[7];
    const float* xproj_w   = (const float*)d_in[8];
    const float* dt_w      = (const float*)d_in[9];
    const float* dt_b      = (const float*)d_in[10];
    const float* A_log     = (const float*)d_in[11];
    const float* D_param   = (const float*)d_in[12];
    const float* out_proj_w= (const float*)d_in[13];
    const float* fnorm_w   = (const float*)d_in[14];
    const float* fnorm_b   = (const float*)d_in[15];
    const float* head_w    = (const float*)d_in[16];
    float* out = (float*)d_out;

    void *ph, *px, *pxz, *pxb, *pxp, *pdl, *py, *pfin;
    cudaGetSymbolAddress(&ph,  g_h);
    cudaGetSymbolAddress(&px,  g_x);
    cudaGetSymbolAddress(&pxz, g_xz);
    cudaGetSymbolAddress(&pxb, g_xb);
    cudaGetSymbolAddress(&pxp, g_xp);
    cudaGetSymbolAddress(&pdl, g_dl);
    cudaGetSymbolAddress(&py,  g_y);
    cudaGetSymbolAddress(&pfin,g_fin);
    float* h  = (float*)ph;   float* x  = (float*)px;
    float* xz = (float*)pxz;  float* xb = (float*)pxb;
    float* xp = (float*)pxp;  float* dl = (float*)pdl;
    float* y  = (float*)py;   float* fin= (float*)pfin;

    embed_k<<<M_TOK, 256>>>(tokens, tok_emb, pos_emb, h);

    for (int i = 0; i < NL_; i++) {
        ln_k<<<M_TOK, 256>>>(h, DM_, x, DM_, ln_w + i*DM_, ln_b + i*DM_);
        // in_proj: 2048 x 4096 x 1024 (512 CTAs)
        gemm_bf16c<<<dim3(32, 16), 256>>>(M_TOK, 2*DI_, DM_,
            x, DM_, in_proj_w + (long)i*2*DI_*DM_, DM_,
            xz, 2*DI_, nullptr, nullptr, 0, 0);
        conv_silu_k<<<(M_TOK*DI_)/256, 256>>>(xz, conv_w + (long)i*DI_*K_, conv_b + (long)i*DI_, xb);
        // xproj: 2048 x 160 x 2048 — split-K 8, atomic accumulate into zeroed xp
        zero_k<<<(M_TOK*XPW_/4 + 255)/256, 256>>>(xp, M_TOK*XPW_/4);
        gemm_bf16c_sk<<<dim3(2, 16, 8), 256>>>(M_TOK, XPW_, DI_/8,
            xb, DI_, xproj_w + (long)i*XPW_*DI_, DI_,
            xp, XPW_);
        // delta = softplus(dt_r @ dtw.T + dtb): 2048 x 2048 x 128
        gemm_bf16c<<<dim3(16, 16), 256>>>(M_TOK, DI_, DTR_,
            xp, XPW_, dt_w + (long)i*DI_*DTR_, DTR_,
            dl, DI_, dt_b + (long)i*DI_, nullptr, 0, 1);
        ssm_scan_k<<<(B_*DI_)/16, 256>>>(xb, xp, dl, xz,
            A_log + (long)i*DI_*N_, D_param + (long)i*DI_, y);
        // out_proj + residual: 2048 x 1024 x 2048 — split-K 2, h already holds residual
        gemm_bf16c_sk<<<dim3(8, 16, 2), 256>>>(M_TOK, DM_, DI_/2,
            y, DI_, out_proj_w + (long)i*DM_*DI_, DI_,
            h, DM_);
    }

    ln_k<<<B_, 256>>>(h + (long)(L_-1)*DM_, (long)L_*DM_, fin, DM_, fnorm_w, fnorm_b);
    head_k<<<P_, 256>>>(fin, head_w, out);
}

// round 11
// speedup vs baseline: 1.3396x; 1.0842x over previous
#include <cuda_runtime.h>
#include <cuda_bf16.h>
#include <math.h>

// Problem constants
#define B_  8
#define L_  256
#define DM_ 1024
#define DI_ 2048
#define N_  16
#define K_  4
#define NL_ 4
#define DTR_ 128
#define P_  97
#define M_TOK (B_*L_)          // 2048 token rows
#define XPW_ (DTR_ + 2*N_)     // 160

// GEMM tiling
#define BM 128
#define BN 128
#define BK 16
#define SST 132                // smem row stride in words ([kp][m] layout, kp = k/2)

// ---------------- scratch (static device globals; no allocation) ----------------
__device__ __align__(16) float g_h [M_TOK*DM_];
__device__ __align__(16) float g_x [M_TOK*DM_];
__device__ __align__(16) float g_xz[M_TOK*2*DI_];
__device__ __align__(16) float g_xb[M_TOK*DI_];
__device__ __align__(16) float g_xp[M_TOK*XPW_];
__device__ __align__(16) float g_dl[M_TOK*DI_];
__device__ __align__(16) float g_y [M_TOK*DI_];
__device__ __align__(16) float g_fin[B_*DM_];

// ---------------- small utils ----------------
__global__ void zero_k(float* __restrict__ p, int n4) {
    int i = blockIdx.x * 256 + threadIdx.x;
    if (i < n4) reinterpret_cast<float4*>(p)[i] = make_float4(0,0,0,0);
}

// ---------------- embedding ----------------
__global__ void embed_k(const int* __restrict__ tok, const float* __restrict__ te,
                        const float* __restrict__ pe, float* __restrict__ h) {
    int row = blockIdx.x;
    int l = row & (L_ - 1);
    int t = tok[row];
    const float* tsrc = te + (long)t * DM_;
    const float* psrc = pe + (long)l * DM_;
    float* dst = h + (long)row * DM_;
    for (int d = threadIdx.x; d < DM_; d += 256)
        dst[d] = tsrc[d] + psrc[d];
}

// ---------------- layernorm ----------------
__global__ void ln_k(const float* __restrict__ in, long istride,
                     float* __restrict__ out, long ostride,
                     const float* __restrict__ w, const float* __restrict__ bb) {
    __shared__ float red[8];
    __shared__ float s_mean, s_rstd;
    int t = threadIdx.x;
    int row = blockIdx.x;
    const float* src = in + (long)row * istride;
    float v[4];
    float s = 0.f;
#pragma unroll
    for (int i = 0; i < 4; i++) { v[i] = src[t + i*256]; s += v[i]; }
#pragma unroll
    for (int o = 16; o; o >>= 1) s += __shfl_xor_sync(~0u, s, o);
    if ((t & 31) == 0) red[t >> 5] = s;
    __syncthreads();
    if (t < 32) {
        float x = (t < 8) ? red[t] : 0.f;
#pragma unroll
        for (int o = 4; o; o >>= 1) x += __shfl_xor_sync(~0u, x, o);
        if (t == 0) s_mean = x * (1.f/DM_);
    }
    __syncthreads();
    float mean = s_mean;
    float q = 0.f;
#pragma unroll
    for (int i = 0; i < 4; i++) { float d = v[i] - mean; q += d * d; }
#pragma unroll
    for (int o = 16; o; o >>= 1) q += __shfl_xor_sync(~0u, q, o);
    if ((t & 31) == 0) red[t >> 5] = q;
    __syncthreads();
    if (t < 32) {
        float x = (t < 8) ? red[t] : 0.f;
#pragma unroll
        for (int o = 4; o; o >>= 1) x += __shfl_xor_sync(~0u, x, o);
        if (t == 0) s_rstd = rsqrtf(x * (1.f/DM_) + 1e-5f);
    }
    __syncthreads();
    float r = s_rstd;
    float* dst = out + (long)row * ostride;
#pragma unroll
    for (int i = 0; i < 4; i++) {
        int idx = t + i*256;
        dst[idx] = (v[i] - mean) * r * w[idx] + bb[idx];
    }
}

// ---------------- bf16 split helpers ----------------
__device__ __forceinline__ uint2 split2_bf16(float x, float y) {
    __nv_bfloat16 hx = __float2bfloat16(x);
    __nv_bfloat16 hy = __float2bfloat16(y);
    float lx = x - __bfloat162float(hx);
    float ly = y - __bfloat162float(hy);
    __nv_bfloat162 hp = __halves2bfloat162(hx, hy);
    __nv_bfloat162 lp = __halves2bfloat162(__float2bfloat16(lx), __float2bfloat16(ly));
    unsigned hw, lw;
    hw = *reinterpret_cast<unsigned*>(&hp);
    lw = *reinterpret_cast<unsigned*>(&lp);
    return make_uint2(hw, lw);
}

__device__ __forceinline__ void mma_bf16(float* c, const unsigned* a, const unsigned* b) {
    asm volatile(
        "mma.sync.aligned.m16n8k16.row.col.f32.bf16.bf16.f32 "
        "{%0,%1,%2,%3}, {%4,%5,%6,%7}, {%8,%9}, {%0,%1,%2,%3};"
        : "+f"(c[0]), "+f"(c[1]), "+f"(c[2]), "+f"(c[3])
        : "r"(a[0]), "r"(a[1]), "r"(a[2]), "r"(a[3]), "r"(b[0]), "r"(b[1]));
}

// fast softplus: v>20 -> v, else log(1+exp(v)) via MUFU
__device__ __forceinline__ float softplus_f(float v) {
    return (v > 20.f) ? v : __logf(1.f + __expf(v));
}

// shared compute body macro: one 128x128x16 step from buffer `cur`
#define GEMM_DEPOSIT(AH, AL, BH, BL)                                                   \
    {                                                                                  \
        uint2 s;                                                                       \
        s = split2_bf16(av0.x, av0.y); AH[kp0*SST + r0] = s.x; AL[kp0*SST + r0] = s.y; \
        s = split2_bf16(av0.z, av0.w); AH[(kp0+1)*SST + r0] = s.x; AL[(kp0+1)*SST + r0] = s.y; \
        s = split2_bf16(av1.x, av1.y); AH[kp0*SST + r0+64] = s.x; AL[kp0*SST + r0+64] = s.y; \
        s = split2_bf16(av1.z, av1.w); AH[(kp0+1)*SST + r0+64] = s.x; AL[(kp0+1)*SST + r0+64] = s.y; \
        s = split2_bf16(bv0.x, bv0.y); BH[kp0*SST + r0] = s.x; BL[kp0*SST + r0] = s.y; \
        s = split2_bf16(bv0.z, bv0.w); BH[(kp0+1)*SST + r0] = s.x; BL[(kp0+1)*SST + r0] = s.y; \
        s = split2_bf16(bv1.x, bv1.y); BH[kp0*SST + r0+64] = s.x; BL[kp0*SST + r0+64] = s.y; \
        s = split2_bf16(bv1.z, bv1.w); BH[(kp0+1)*SST + r0+64] = s.x; BL[(kp0+1)*SST + r0+64] = s.y; \
    }

#define GEMM_COMPUTE(AH, AL, BH, BL)                                                   \
    {                                                                                  \
        unsigned bh[4][2], bl[4][2];                                                   \
        _Pragma("unroll")                                                              \
        for (int j = 0; j < 4; j++) {                                                  \
            int n = warpN + j*8 + grp;                                                 \
            bh[j][0] = BH[tig*SST + n];                                                \
            bh[j][1] = BH[(tig+4)*SST + n];                                            \
            bl[j][0] = BL[tig*SST + n];                                                \
            bl[j][1] = BL[(tig+4)*SST + n];                                            \
        }                                                                              \
        _Pragma("unroll")                                                              \
        for (int i = 0; i < 4; i++) {                                                  \
            int m = warpM + i*16 + grp;                                                \
            unsigned ah[4], al[4];                                                     \
            ah[0] = AH[tig*SST + m];     ah[1] = AH[tig*SST + m + 8];                  \
            ah[2] = AH[(tig+4)*SST + m]; ah[3] = AH[(tig+4)*SST + m + 8];              \
            al[0] = AL[tig*SST + m];     al[1] = AL[tig*SST + m + 8];                  \
            al[2] = AL[(tig+4)*SST + m]; al[3] = AL[(tig+4)*SST + m + 8];              \
            _Pragma("unroll")                                                          \
            for (int j = 0; j < 4; j++) mma_bf16(acc[i][j], ah, bh[j]);                \
            _Pragma("unroll")                                                          \
            for (int j = 0; j < 4; j++) mma_bf16(acc[i][j], ah, bl[j]);                \
            _Pragma("unroll")                                                          \
            for (int j = 0; j < 4; j++) mma_bf16(acc[i][j], al, bh[j]);                \
        }                                                                              \
    }

// ---------------- bf16x2 compensated GEMM (double-buffered, deposit-early) ----------------
// Per k-tile: load(k+1) -> deposit(k+1) -> compute(k) -> sync.
// Prefetch registers live only load->deposit (short), eliminating spills.
__global__ __launch_bounds__(256, 2)
void gemm_bf16c(int M, int N, int Kd,
                const float* __restrict__ A, int lda,
                const float* __restrict__ W, int ldb,
                float* __restrict__ C, int ldc,
                const float* __restrict__ bias,
                const float* __restrict__ add, int ldadd,
                int act) {
    __shared__ unsigned Ahp[2][8*SST], Alp[2][8*SST];
    __shared__ unsigned Bhp[2][8*SST], Blp[2][8*SST];
    int tid = threadIdx.x;
    int lane = tid & 31, wid = tid >> 5;
    int warpM = (wid >> 2) * 64;
    int warpN = (wid & 3) * 32;
    int grp = lane >> 2, tig = lane & 3;

    int r0 = tid >> 2;
    int c4 = (tid & 3) * 4;
    int kp0 = c4 >> 1;
    int gAr0 = blockIdx.y * BM + r0, gAr1 = gAr0 + 64;
    int gBr0 = blockIdx.x * BN + r0, gBr1 = gBr0 + 64;
    bool aOK0 = gAr0 < M, aOK1 = gAr1 < M;
    bool bOK0 = gBr0 < N, bOK1 = gBr1 < N;
    const float* Ap0 = A + (long)gAr0 * lda + c4;
    const float* Ap1 = A + (long)gAr1 * lda + c4;
    const float* Wp0 = W + (long)gBr0 * ldb + c4;
    const float* Wp1 = W + (long)gBr1 * ldb + c4;

    float acc[4][4][4];
#pragma unroll
    for (int i = 0; i < 4; i++)
#pragma unroll
        for (int j = 0; j < 4; j++)
#pragma unroll
            for (int q = 0; q < 4; q++) acc[i][j][q] = 0.f;

    const float4 z4 = make_float4(0,0,0,0);

    {   // prologue: stage 0
        float4 av0 = aOK0 ? *(const float4*)(Ap0) : z4;
        float4 av1 = aOK1 ? *(const float4*)(Ap1) : z4;
        float4 bv0 = bOK0 ? *(const float4*)(Wp0) : z4;
        float4 bv1 = bOK1 ? *(const float4*)(Wp1) : z4;
        GEMM_DEPOSIT(Ahp[0], Alp[0], Bhp[0], Blp[0]);
    }
    __syncthreads();

    int nst = Kd / BK;
    for (int kt = 0; kt < nst; kt++) {
        int cur = kt & 1;
        bool pf = (kt + 1) < nst;
        if (pf) {
            int k0 = (kt + 1) * BK;
            float4 av0 = aOK0 ? *(const float4*)(Ap0 + k0) : z4;
            float4 av1 = aOK1 ? *(const float4*)(Ap1 + k0) : z4;
            float4 bv0 = bOK0 ? *(const float4*)(Wp0 + k0) : z4;
            float4 bv1 = bOK1 ? *(const float4*)(Wp1 + k0) : z4;
            if (cur == 0) { GEMM_DEPOSIT(Ahp[1], Alp[1], Bhp[1], Blp[1]); }
            else          { GEMM_DEPOSIT(Ahp[0], Alp[0], Bhp[0], Blp[0]); }
        }
        if (cur == 0) { GEMM_COMPUTE(Ahp[0], Alp[0], Bhp[0], Blp[0]); }
        else          { GEMM_COMPUTE(Ahp[1], Alp[1], Bhp[1], Blp[1]); }
        if (pf) __syncthreads();
    }

#pragma unroll
    for (int i = 0; i < 4; i++) {
        int gm0 = blockIdx.y * BM + warpM + i*16 + grp;
#pragma unroll
        for (int j = 0; j < 4; j++) {
            int gn = blockIdx.x * BN + warpN + j*8 + 2*tig;
#pragma unroll
            for (int half = 0; half < 2; half++) {
                int gm = gm0 + half*8;
                if (gm >= M) continue;
#pragma unroll
                for (int q = 0; q < 2; q++) {
                    int n = gn + q;
                    if (n >= N) continue;
                    float v = acc[i][j][half*2 + q];
                    if (bias) v += bias[n];
                    if (act == 1) v = softplus_f(v);
                    if (add) v += add[(long)gm * ldadd + n];
                    C[(long)gm * ldc + n] = v;
                }
            }
        }
    }
}

// ---------------- split-K variant: C += partial (atomicAdd epilogue) ----------------
__global__ __launch_bounds__(256, 2)
void gemm_bf16c_sk(int M, int N, int kcnt,
                   const float* __restrict__ A, int lda,
                   const float* __restrict__ W, int ldb,
                   float* __restrict__ C, int ldc) {
    __shared__ unsigned Ahp[2][8*SST], Alp[2][8*SST];
    __shared__ unsigned Bhp[2][8*SST], Blp[2][8*SST];
    int tid = threadIdx.x;
    int lane = tid & 31, wid = tid >> 5;
    int warpM = (wid >> 2) * 64;
    int warpN = (wid & 3) * 32;
    int grp = lane >> 2, tig = lane & 3;

    long kbeg = (long)blockIdx.z * kcnt;
    A += kbeg; W += kbeg;

    int r0 = tid >> 2;
    int c4 = (tid & 3) * 4;
    int kp0 = c4 >> 1;
    int gAr0 = blockIdx.y * BM + r0, gAr1 = gAr0 + 64;
    int gBr0 = blockIdx.x * BN + r0, gBr1 = gBr0 + 64;
    bool aOK0 = gAr0 < M, aOK1 = gAr1 < M;
    bool bOK0 = gBr0 < N, bOK1 = gBr1 < N;
    const float* Ap0 = A + (long)gAr0 * lda + c4;
    const float* Ap1 = A + (long)gAr1 * lda + c4;
    const float* Wp0 = W + (long)gBr0 * ldb + c4;
    const float* Wp1 = W + (long)gBr1 * ldb + c4;

    float acc[4][4][4];
#pragma unroll
    for (int i = 0; i < 4; i++)
#pragma unroll
        for (int j = 0; j < 4; j++)
#pragma unroll
            for (int q = 0; q < 4; q++) acc[i][j][q] = 0.f;

    const float4 z4 = make_float4(0,0,0,0);

    {   // prologue: stage 0
        float4 av0 = aOK0 ? *(const float4*)(Ap0) : z4;
        float4 av1 = aOK1 ? *(const float4*)(Ap1) : z4;
        float4 bv0 = bOK0 ? *(const float4*)(Wp0) : z4;
        float4 bv1 = bOK1 ? *(const float4*)(Wp1) : z4;
        GEMM_DEPOSIT(Ahp[0], Alp[0], Bhp[0], Blp[0]);
    }
    __syncthreads();

    int nst = kcnt / BK;
    for (int kt = 0; kt < nst; kt++) {
        int cur = kt & 1;
        bool pf = (kt + 1) < nst;
        if (pf) {
            int k0 = (kt + 1) * BK;
            float4 av0 = aOK0 ? *(const float4*)(Ap0 + k0) : z4;
            float4 av1 = aOK1 ? *(const float4*)(Ap1 + k0) : z4;
            float4 bv0 = bOK0 ? *(const float4*)(Wp0 + k0) : z4;
            float4 bv1 = bOK1 ? *(const float4*)(Wp1 + k0) : z4;
            if (cur == 0) { GEMM_DEPOSIT(Ahp[1], Alp[1], Bhp[1], Blp[1]); }
            else          { GEMM_DEPOSIT(Ahp[0], Alp[0], Bhp[0], Blp[0]); }
        }
        if (cur == 0) { GEMM_COMPUTE(Ahp[0], Alp[0], Bhp[0], Blp[0]); }
        else          { GEMM_COMPUTE(Ahp[1], Alp[1], Bhp[1], Blp[1]); }
        if (pf) __syncthreads();
    }

#pragma unroll
    for (int i = 0; i < 4; i++) {
        int gm0 = blockIdx.y * BM + warpM + i*16 + grp;
#pragma unroll
        for (int j = 0; j < 4; j++) {
            int gn = blockIdx.x * BN + warpN + j*8 + 2*tig;
#pragma unroll
            for (int half = 0; half < 2; half++) {
                int gm = gm0 + half*8;
                if (gm >= M) continue;
#pragma unroll
                for (int q = 0; q < 2; q++) {
                    int n = gn + q;
                    if (n >= N) continue;
                    atomicAdd(&C[(long)gm * ldc + n], acc[i][j][half*2 + q]);
                }
            }
        }
    }
}

// ---------------- causal depthwise conv (K=4) + SiLU (fast sigmoid) ----------------
__global__ void conv_silu_k(const float* __restrict__ xz, const float* __restrict__ cw,
                            const float* __restrict__ cb, float* __restrict__ xb) {
    long idx = (long)blockIdx.x * 256 + threadIdx.x;
    int d = idx & (DI_ - 1);
    long bl = idx >> 11;
    int l = (int)(bl & (L_ - 1));
    float acc = cb[d];
#pragma unroll
    for (int k = 0; k < K_; k++) {
        int lp = l + k - (K_ - 1);
        if (lp >= 0)
            acc = fmaf(cw[d*K_ + k], xz[(bl + (k - (K_-1))) * (2*DI_) + d], acc);
    }
    acc = __fdividef(acc, 1.f + __expf(-acc));
    xb[idx] = acc;
}

// ---------------- selective SSM scan + D skip + z-gating (fast exp) ----------------
__global__ void ssm_scan_k(const float* __restrict__ xb, const float* __restrict__ xp,
                           const float* __restrict__ dl, const float* __restrict__ xz,
                           const float* __restrict__ Alog, const float* __restrict__ Dp,
                           float* __restrict__ y) {
    int t = threadIdx.x;
    int g = t >> 4, lane = t & 15;
    int ch = blockIdx.x * 16 + g;
    int b = ch >> 11;
    int d = ch & (DI_ - 1);
    float A = -__expf(Alog[d*N_ + lane]);
    float Dv = Dp[d];
    float h = 0.f;
    long rowbase = (long)b * L_;
    const float* dlp = dl + rowbase*DI_ + d;
    const float* xbp = xb + rowbase*DI_ + d;
    const float* Bp  = xp + rowbase*XPW_ + DTR_ + lane;
    const float* zp  = xz + rowbase*(2*DI_) + DI_ + d;
    float* yp = y + rowbase*DI_ + d;
    for (int l = 0; l < L_; l++) {
        float dv = dlp[(long)l*DI_];
        float xv = xbp[(long)l*DI_];
        float Bv = Bp[(long)l*XPW_];
        float Cv = Bp[(long)l*XPW_ + N_];
        h = fmaf(__expf(dv * A), h, dv * Bv * xv);
        float c = h * Cv;
        c += __shfl_xor_sync(~0u, c, 8);
        c += __shfl_xor_sync(~0u, c, 4);
        c += __shfl_xor_sync(~0u, c, 2);
        c += __shfl_xor_sync(~0u, c, 1);
        if (lane == 0) {
            float z = zp[(long)l*(2*DI_)];
            float yv = c + xv * Dv;
            yp[(long)l*DI_] = yv * __fdividef(z, 1.f + __expf(-z));
        }
    }
}

// ---------------- head ----------------
__global__ void head_k(const float* __restrict__ fin, const float* __restrict__ hw,
                       float* __restrict__ out) {
    int wid = blockIdx.x * 8 + (threadIdx.x >> 5);
    int lane = threadIdx.x & 31;
    if (wid >= B_ * P_) return;
    int b = wid / P_, p = wid % P_;
    const float* a = fin + (long)b * DM_;
    const float* w = hw + (long)p * DM_;
    float s = 0.f;
    for (int k = lane; k < DM_; k += 32) s = fmaf(a[k], w[k], s);
#pragma unroll
    for (int o = 16; o; o >>= 1) s += __shfl_xor_sync(~0u, s, o);
    if (lane == 0) out[wid] = s;
}

// ---------------- launch ----------------
extern "C" void kernel_launch(void* const* d_in, const int* in_sizes, int n_in,
                              void* d_out, int out_size) {
    const int*   tokens    = (const int*)  d_in[0];
    const float* tok_emb   = (const float*)d_in[1];
    const float* pos_emb   = (const float*)d_in[2];
    const float* ln_w      = (const float*)d_in[3];
    const float* ln_b      = (const float*)d_in[4];
    const float* in_proj_w = (const float*)d_in[5];
    const float* conv_w    = (const float*)d_in[6];
    const float* conv_b    = (const float*)d_in[7];
    const float* xproj_w   = (const float*)d_in[8];
    const float* dt_w      = (const float*)d_in[9];
    const float* dt_b      = (const float*)d_in[10];
    const float* A_log     = (const float*)d_in[11];
    const float* D_param   = (const float*)d_in[12];
    const float* out_proj_w= (const float*)d_in[13];
    const float* fnorm_w   = (const float*)d_in[14];
    const float* fnorm_b   = (const float*)d_in[15];
    const float* head_w    = (const float*)d_in[16];
    float* out = (float*)d_out;

    void *ph, *px, *pxz, *pxb, *pxp, *pdl, *py, *pfin;
    cudaGetSymbolAddress(&ph,  g_h);
    cudaGetSymbolAddress(&px,  g_x);
    cudaGetSymbolAddress(&pxz, g_xz);
    cudaGetSymbolAddress(&pxb, g_xb);
    cudaGetSymbolAddress(&pxp, g_xp);
    cudaGetSymbolAddress(&pdl, g_dl);
    cudaGetSymbolAddress(&py,  g_y);
    cudaGetSymbolAddress(&pfin,g_fin);
    float* h  = (float*)ph;   float* x  = (float*)px;
    float* xz = (float*)pxz;  float* xb = (float*)pxb;
    float* xp = (float*)pxp;  float* dl = (float*)pdl;
    float* y  = (float*)py;   float* fin= (float*)pfin;

    embed_k<<<M_TOK, 256>>>(tokens, tok_emb, pos_emb, h);

    for (int i = 0; i < NL_; i++) {
        ln_k<<<M_TOK, 256>>>(h, DM_, x, DM_, ln_w + i*DM_, ln_b + i*DM_);
        // in_proj: 2048 x 4096 x 1024 (512 CTAs)
        gemm_bf16c<<<dim3(32, 16), 256>>>(M_TOK, 2*DI_, DM_,
            x, DM_, in_proj_w + (long)i*2*DI_*DM_, DM_,
            xz, 2*DI_, nullptr, nullptr, 0, 0);
        conv_silu_k<<<(M_TOK*DI_)/256, 256>>>(xz, conv_w + (long)i*DI_*K_, conv_b + (long)i*DI_, xb);
        // xproj: 2048 x 160 x 2048 — split-K 8, atomic accumulate into zeroed xp
        zero_k<<<(M_TOK*XPW_/4 + 255)/256, 256>>>(xp, M_TOK*XPW_/4);
        gemm_bf16c_sk<<<dim3(2, 16, 8), 256>>>(M_TOK, XPW_, DI_/8,
            xb, DI_, xproj_w + (long)i*XPW_*DI_, DI_,
            xp, XPW_);
        // delta = softplus(dt_r @ dtw.T + dtb): 2048 x 2048 x 128
        gemm_bf16c<<<dim3(16, 16), 256>>>(M_TOK, DI_, DTR_,
            xp, XPW_, dt_w + (long)i*DI_*DTR_, DTR_,
            dl, DI_, dt_b + (long)i*DI_, nullptr, 0, 1);
        ssm_scan_k<<<(B_*DI_)/16, 256>>>(xb, xp, dl, xz,
            A_log + (long)i*DI_*N_, D_param + (long)i*DI_, y);
        // out_proj + residual: 2048 x 1024 x 2048 — split-K 2, h already holds residual
        gemm_bf16c_sk<<<dim3(8, 16, 2), 256>>>(M_TOK, DM_, DI_/2,
            y, DI_, out_proj_w + (long)i*DM_*DI_, DI_,
            h, DM_);
    }

    ln_k<<<B_, 256>>>(h + (long)(L_-1)*DM_, (long)L_*DM_, fin, DM_, fnorm_w, fnorm_b);
    head_k<<<P_, 256>>>(fin, head_w, out);
}